// round 1
// baseline (speedup 1.0000x reference)
#include <cuda_runtime.h>

// SSIM, fully fused single pass.
// X,Y: f32[32,3,512,512]. Output: scalar mean SSIM (f32).
//
// Per block: one image tile of 128 output cols x 32 output rows.
// Phase 1: horizontal 11-tap Gaussian conv of {x, y, x^2, y^2, xy} -> smem (5 x 42 x 128 f32).
// Phase 2: vertical 11-tap conv with 4x4x5 register blocking per thread + SSIM epilogue
//          + block reduction -> atomicAdd(double) into a __device__ accumulator.
// Normalization (v+1)/2 is folded algebraically: mu' = (mu+1)/2, sigma' = sigma_raw/4.

#define TW 128           // output cols per block tile
#define TH 32            // output rows per block tile
#define NHR (TH + 10)    // horizontal rows needed (42)
#define BX 32
#define BY 8

__device__ double g_ssim_accum;

__global__ void ssim_zero_kernel() { g_ssim_accum = 0.0; }

__global__ void ssim_final_kernel(float* __restrict__ out, double inv_count) {
    out[0] = (float)(g_ssim_accum * inv_count);
}

__global__ void __launch_bounds__(BX * BY, 2)
ssim_main_kernel(const float* __restrict__ X, const float* __restrict__ Y) {
    extern __shared__ float sh[];  // [5][NHR][TW] floats = 107520 B

    // Gaussian(11, sigma=1.5), normalized. Compile-time constants -> FFMA-imm form.
    const float GW[11] = {
        0.00102838f, 0.00759876f, 0.03600079f, 0.10936072f, 0.21300555f,
        0.26601173f,
        0.21300555f, 0.10936072f, 0.03600079f, 0.00759876f, 0.00102838f};

    const int tx = threadIdx.x;
    const int ty = threadIdx.y;
    const int c0 = blockIdx.x * TW;
    const int r0 = blockIdx.y * TH;
    const long img = blockIdx.z;
    const float* __restrict__ Xi = X + img * (512L * 512L);
    const float* __restrict__ Yi = Y + img * (512L * 512L);
    const int basec = c0 + 4 * tx;

    // ---------------- Phase 1: horizontal pass into smem ----------------
    for (int hr = ty; hr < NHR; hr += BY) {
        const int gr = r0 + hr;
        if (gr < 512) {
            float xv[16], yv[16];
            const float* __restrict__ xr = Xi + (long)gr * 512;
            const float* __restrict__ yr = Yi + (long)gr * 512;
#pragma unroll
            for (int q = 0; q < 4; q++) {
                const int qc = basec + 4 * q;
                float4 xq, yq;
                if (qc < 512) {  // qc is a multiple of 4 -> qc+3 <= 511
                    xq = *reinterpret_cast<const float4*>(xr + qc);
                    yq = *reinterpret_cast<const float4*>(yr + qc);
                } else {
                    xq = make_float4(0.f, 0.f, 0.f, 0.f);
                    yq = make_float4(0.f, 0.f, 0.f, 0.f);
                }
                xv[4 * q + 0] = xq.x; xv[4 * q + 1] = xq.y;
                xv[4 * q + 2] = xq.z; xv[4 * q + 3] = xq.w;
                yv[4 * q + 0] = yq.x; yv[4 * q + 1] = yq.y;
                yv[4 * q + 2] = yq.z; yv[4 * q + 3] = yq.w;
            }
            float pxx[14], pyy[14], pxy[14];
#pragma unroll
            for (int k = 0; k < 14; k++) {
                pxx[k] = xv[k] * xv[k];
                pyy[k] = yv[k] * yv[k];
                pxy[k] = xv[k] * yv[k];
            }
            float hx[4], hy[4], hxx[4], hyy[4], hxy[4];
#pragma unroll
            for (int j = 0; j < 4; j++) {
                float a0 = 0.f, a1 = 0.f, a2 = 0.f, a3 = 0.f, a4 = 0.f;
#pragma unroll
                for (int k = 0; k < 11; k++) {
                    const float w = GW[k];
                    a0 = fmaf(w, xv[j + k], a0);
                    a1 = fmaf(w, yv[j + k], a1);
                    a2 = fmaf(w, pxx[j + k], a2);
                    a3 = fmaf(w, pyy[j + k], a3);
                    a4 = fmaf(w, pxy[j + k], a4);
                }
                hx[j] = a0; hy[j] = a1; hxx[j] = a2; hyy[j] = a3; hxy[j] = a4;
            }
            const int so = hr * TW + 4 * tx;
            *reinterpret_cast<float4*>(&sh[0 * NHR * TW + so]) = make_float4(hx[0], hx[1], hx[2], hx[3]);
            *reinterpret_cast<float4*>(&sh[1 * NHR * TW + so]) = make_float4(hy[0], hy[1], hy[2], hy[3]);
            *reinterpret_cast<float4*>(&sh[2 * NHR * TW + so]) = make_float4(hxx[0], hxx[1], hxx[2], hxx[3]);
            *reinterpret_cast<float4*>(&sh[3 * NHR * TW + so]) = make_float4(hyy[0], hyy[1], hyy[2], hyy[3]);
            *reinterpret_cast<float4*>(&sh[4 * NHR * TW + so]) = make_float4(hxy[0], hxy[1], hxy[2], hxy[3]);
        }
    }
    __syncthreads();

    // ---------------- Phase 2: vertical pass + SSIM + reduction ----------------
    float acc[5][4][4];  // [map][vrow][col]
#pragma unroll
    for (int m = 0; m < 5; m++)
#pragma unroll
        for (int v = 0; v < 4; v++)
#pragma unroll
            for (int c = 0; c < 4; c++) acc[m][v][c] = 0.0f;

    const int lr0 = ty * 4;
#pragma unroll
    for (int i = 0; i < 14; i++) {
        float hv[5][4];
#pragma unroll
        for (int m = 0; m < 5; m++) {
            const float4 t = *reinterpret_cast<const float4*>(
                &sh[(m * NHR + lr0 + i) * TW + 4 * tx]);
            hv[m][0] = t.x; hv[m][1] = t.y; hv[m][2] = t.z; hv[m][3] = t.w;
        }
#pragma unroll
        for (int v = 0; v < 4; v++) {
            const int k = i - v;
            if (k >= 0 && k <= 10) {
                const float w = GW[k];
#pragma unroll
                for (int m = 0; m < 5; m++)
#pragma unroll
                    for (int c = 0; c < 4; c++)
                        acc[m][v][c] = fmaf(w, hv[m][c], acc[m][v][c]);
            }
        }
    }

    float lsum = 0.0f;
    const float C1 = 1e-4f;      // (0.01*1)^2
    const float C2x4 = 0.0036f;  // 4 * (0.03*1)^2 (sigmas kept unscaled by 1/4)
#pragma unroll
    for (int v = 0; v < 4; v++) {
        const int orow = r0 + lr0 + v;
#pragma unroll
        for (int c = 0; c < 4; c++) {
            const int ocol = basec + c;
            const float mu1 = acc[0][v][c];
            const float mu2 = acc[1][v][c];
            const float s1 = fmaf(-mu1, mu1, acc[2][v][c]);   // 4*sigma1_sq'
            const float s2 = fmaf(-mu2, mu2, acc[3][v][c]);   // 4*sigma2_sq'
            const float s12 = fmaf(-mu1, mu2, acc[4][v][c]);  // 4*sigma12'
            const float mu1p = fmaf(0.5f, mu1, 0.5f);
            const float mu2p = fmaf(0.5f, mu2, 0.5f);
            const float csn = fmaf(2.0f, s12, C2x4);
            const float csd = s1 + s2 + C2x4;
            const float t = mu1p * mu2p;
            const float ln = fmaf(2.0f, t, C1);
            const float ld = fmaf(mu1p, mu1p, fmaf(mu2p, mu2p, C1));
            const float ssim = (csn * ln) * __fdividef(1.0f, csd * ld);
            lsum += (orow < 502 && ocol < 502) ? ssim : 0.0f;
        }
    }

#pragma unroll
    for (int off = 16; off > 0; off >>= 1)
        lsum += __shfl_xor_sync(0xffffffffu, lsum, off);

    __shared__ float wsum[BY];
    if (tx == 0) wsum[ty] = lsum;
    __syncthreads();
    if (tx == 0 && ty == 0) {
        float b = 0.0f;
#pragma unroll
        for (int w = 0; w < BY; w++) b += wsum[w];
        atomicAdd(&g_ssim_accum, (double)b);
    }
}

extern "C" void kernel_launch(void* const* d_in, const int* in_sizes, int n_in,
                              void* d_out, int out_size) {
    const float* X = (const float*)d_in[0];
    const float* Y = (const float*)d_in[1];
    float* out = (float*)d_out;

    const int images = in_sizes[0] / (512 * 512);  // N*C = 96
    const double count = (double)images * 502.0 * 502.0;

    const size_t smem = 5 * NHR * TW * sizeof(float);  // 107520 B
    cudaFuncSetAttribute(ssim_main_kernel,
                         cudaFuncAttributeMaxDynamicSharedMemorySize, (int)smem);

    ssim_zero_kernel<<<1, 1>>>();
    dim3 grid(4, (502 + TH - 1) / TH, images);  // 4 col-tiles x 16 row-slabs x 96 images
    dim3 block(BX, BY);
    ssim_main_kernel<<<grid, block, smem>>>(X, Y);
    ssim_final_kernel<<<1, 1>>>(out, 1.0 / count);
}